// round 15
// baseline (speedup 1.0000x reference)
#include <cuda_runtime.h>
#include <cuda_fp16.h>
#include <math.h>

#define NN 30000
#define EE 480000
#define GG 512

// pair counts / weight offsets
#define NPX (NN * 64)          // x pairs (K=128)
#define NW1 (512 * 64)         // W1T pairs: N=512, KP=64
#define NW2 (256 * 256)        // W2T pairs: N=256, KP=256
#define NW3 (64 * 128)         // W3T pairs: N=64,  KP=128
#define OFF1 0
#define OFF2 (NW1)
#define OFF3 (NW1 + NW2)

// ---------------- scratch (static device globals; no allocation) ------------
__device__ unsigned g_h[(size_t)NN * 256];     // GEMM output, half2-packed
__device__ unsigned g_ah[(size_t)NN * 256];    // activations, fp16x2 single plane
__device__ unsigned g_wt[NW1 + NW2 + NW3];     // weights(T), fp16x2 single plane
__device__ float g_as[NN * 8];
__device__ float g_ad[NN * 8];
__device__ int   g_cnt[NN];
__device__ int   g_rowptr[NN + 1];
__device__ int   g_cur[NN];
__device__ int   g_col[EE];
__device__ float g_gsum[GG * 64];
__device__ unsigned g_gmax[GG * 64];
__device__ int   g_gcnt[GG];

// ---------------- helpers ----------------------------------------------------
__device__ __forceinline__ unsigned fenc(float f) {
    unsigned b = __float_as_uint(f);
    return (b & 0x80000000u) ? ~b : (b | 0x80000000u);
}
__device__ __forceinline__ float fdec(unsigned u) {
    return __uint_as_float((u & 0x80000000u) ? (u & 0x7fffffffu) : ~u);
}
__device__ __forceinline__ unsigned hpk2(float x, float y) {
    half2 v = __floats2half2_rn(x, y);
    return *(unsigned*)&v;
}
__device__ __forceinline__ void mma_f16(float c[4], const unsigned a[4],
                                        unsigned b0, unsigned b1) {
    asm volatile(
        "mma.sync.aligned.m16n8k16.row.col.f32.f16.f16.f32 "
        "{%0,%1,%2,%3}, {%4,%5,%6,%7}, {%8,%9}, {%0,%1,%2,%3};"
        : "+f"(c[0]), "+f"(c[1]), "+f"(c[2]), "+f"(c[3])
        : "r"(a[0]), "r"(a[1]), "r"(a[2]), "r"(a[3]), "r"(b0), "r"(b1));
}
__device__ __forceinline__ void ldsm_x4(unsigned& r0, unsigned& r1,
                                        unsigned& r2, unsigned& r3, unsigned addr) {
    asm volatile(
        "ldmatrix.sync.aligned.m8n8.x4.shared.b16 {%0,%1,%2,%3}, [%4];"
        : "=r"(r0), "=r"(r1), "=r"(r2), "=r"(r3) : "r"(addr));
}
__device__ __forceinline__ void cp_async16(unsigned dst, const void* src, int sz) {
    asm volatile("cp.async.cg.shared.global [%0], [%1], 16, %2;"
                 :: "r"(dst), "l"(src), "r"(sz) : "memory");
}
__device__ __forceinline__ void cp_commit() {
    asm volatile("cp.async.commit_group;" ::: "memory");
}
__device__ __forceinline__ void cp_wait2() {
    asm volatile("cp.async.wait_group 2;" ::: "memory");
}

// ---------------- prep: fp16 x + fp16 weights(T), zero counters ---------------
__global__ void k_prep(const float* __restrict__ x,
                       const float* __restrict__ W1,
                       const float* __restrict__ W2,
                       const float* __restrict__ W3) {
    int i = blockIdx.x * blockDim.x + threadIdx.x;
    if (i < NN) g_cnt[i] = 0;
    if (i < GG * 64) {
        g_gsum[i] = 0.f;
        g_gmax[i] = 0x007FFFFFu;  // fenc(-inf)
    }
    if (i < GG) g_gcnt[i] = 0;
    if (i < NPX) {
        float2 v = *(const float2*)(x + 2 * (size_t)i);
        g_ah[i] = hpk2(v.x, v.y);
    } else {
        int j = i - NPX;
        if (j < NW1) {
            int n = j >> 6, kp = j & 63;
            g_wt[OFF1 + n * 64 + kp] =
                hpk2(W1[(2 * kp) * 512 + n], W1[(2 * kp + 1) * 512 + n]);
        } else if ((j -= NW1) < NW2) {
            int n = j >> 8, kp = j & 255;
            g_wt[OFF2 + n * 256 + kp] =
                hpk2(W2[(2 * kp) * 256 + n], W2[(2 * kp + 1) * 256 + n]);
        } else if ((j -= NW2) < NW3) {
            int n = j >> 7, kp = j & 127;
            g_wt[OFF3 + n * 128 + kp] =
                hpk2(W3[(2 * kp) * 64 + n], W3[(2 * kp + 1) * 64 + n]);
        }
    }
}

// ---------------- CSR build ---------------------------------------------------
__global__ void k_count(const int* __restrict__ dst) {
    int e = blockIdx.x * blockDim.x + threadIdx.x;
    if (e < EE) atomicAdd(&g_cnt[dst[e]], 1);
}
__global__ void k_scan() {
    __shared__ int wsum[32];
    __shared__ int carry_s;
    int t = threadIdx.x;
    int lane = t & 31, wid = t >> 5;
    if (t == 0) carry_s = 0;
    __syncthreads();
    for (int base = 0; base < NN; base += 1024) {
        int i = base + t;
        int v = (i < NN) ? g_cnt[i] : 0;
        int x = v;
#pragma unroll
        for (int o = 1; o < 32; o <<= 1) {
            int u = __shfl_up_sync(0xffffffffu, x, o);
            if (lane >= o) x += u;
        }
        if (lane == 31) wsum[wid] = x;
        __syncthreads();
        if (wid == 0) {
            int s = wsum[lane];
#pragma unroll
            for (int o = 1; o < 32; o <<= 1) {
                int u = __shfl_up_sync(0xffffffffu, s, o);
                if (lane >= o) s += u;
            }
            wsum[lane] = s;
        }
        __syncthreads();
        int woff = (wid == 0) ? 0 : wsum[wid - 1];
        int ex = carry_s + woff + x - v;
        if (i < NN) {
            g_rowptr[i] = ex;
            g_cur[i] = ex;
        }
        int tot = wsum[31];
        __syncthreads();
        if (t == 0) carry_s += tot;
        __syncthreads();
    }
    if (t == 0) g_rowptr[NN] = carry_s;
}
__global__ void k_scatter(const int* __restrict__ src, const int* __restrict__ dst) {
    int e = blockIdx.x * blockDim.x + threadIdx.x;
    if (e < EE) {
        int p = atomicAdd(&g_cur[dst[e]], 1);
        g_col[p] = src[e];
    }
}

// ---------------- single-pass fp16 GEMM, cp.async 4-stage --------------------
#define BM 128
#define BN 128
#define BK 16
#define NSTAGE 4
#define STAGE_U32 1536
#define STAGE_BYTES (STAGE_U32 * 4)

__global__ __launch_bounds__(256, 2) void k_gemm_tc(const unsigned* __restrict__ A,
                                                    const unsigned* __restrict__ Bt,
                                                    unsigned* __restrict__ C,
                                                    const float* __restrict__ aw_s,
                                                    const float* __restrict__ aw_d,
                                                    int M, int N, int K) {
    extern __shared__ __align__(16) unsigned dynsmem[];
    unsigned* As  = dynsmem;                         // [NSTAGE][128][12]
    unsigned* Bts = dynsmem + NSTAGE * STAGE_U32;

    const int tid = threadIdx.x;
    const int lane = tid & 31;
    const int warp = tid >> 5;
    const int wm = (warp >> 1) * 32;
    const int wn = (warp & 1) * 64;
    const int row0 = blockIdx.y * BM;
    const int col0 = blockIdx.x * BN;
    const int KP = K >> 1;

    float acc[2][8][4];
#pragma unroll
    for (int mf = 0; mf < 2; mf++)
#pragma unroll
        for (int nf = 0; nf < 8; nf++)
#pragma unroll
            for (int r = 0; r < 4; r++) acc[mf][nf][r] = 0.f;

    const int ar = tid >> 1;
    const int au0 = (tid & 1) * 4;
    const int agr = row0 + ar;
    const bool aok = (agr < M);
    const int asz = aok ? 16 : 0;
    const int colB = tid & 127;
    const int kpg = (tid >> 7) * 4;
    const int bgc = col0 + colB;
    const bool bok = (bgc < N);
    const int bsz = bok ? 16 : 0;

    const unsigned* a_src = A  + (size_t)(aok ? agr : 0) * KP + au0;
    const unsigned* b_src = Bt + (size_t)(bok ? bgc : 0) * KP + kpg;

    const unsigned d_a = (unsigned)__cvta_generic_to_shared(&As[ar * 12 + au0]);
    const unsigned d_b = (unsigned)__cvta_generic_to_shared(&Bts[colB * 12 + kpg]);

#define ISSUE(s, kb)                                              \
    do {                                                          \
        unsigned o = (unsigned)(s) * STAGE_BYTES;                 \
        cp_async16(d_a + o, a_src + (kb), asz);                   \
        cp_async16(d_b + o, b_src + (kb), bsz);                   \
    } while (0)

    const int arow = ((lane >> 3) & 1) * 8 + (lane & 7);
    const int aucol = (lane >> 4) * 4;
    unsigned aaddr[2];
#pragma unroll
    for (int mf = 0; mf < 2; mf++)
        aaddr[mf] = (unsigned)__cvta_generic_to_shared(
            &As[(wm + mf * 16 + arow) * 12 + aucol]);
    const int bcol = ((lane >> 4) & 1) * 8 + (lane & 7);
    const int bucol = ((lane >> 3) & 1) * 4;
    unsigned baddr = (unsigned)__cvta_generic_to_shared(&Bts[(wn + bcol) * 12 + bucol]);

    const int nIter = K / BK;
    ISSUE(0, 0);
    cp_commit();
    ISSUE(1, 8);
    cp_commit();

    for (int it = 0; it < nIter; it++) {
        if (it + 2 < nIter) ISSUE((it + 2) & 3, (it + 2) * 8);
        cp_commit();
        cp_wait2();
        __syncthreads();

        const unsigned soff = (unsigned)(it & 3) * STAGE_BYTES;
        unsigned a[2][4];
#pragma unroll
        for (int mf = 0; mf < 2; mf++)
            ldsm_x4(a[mf][0], a[mf][1], a[mf][2], a[mf][3], aaddr[mf] + soff);
#pragma unroll
        for (int p = 0; p < 4; p++) {
            unsigned b0, b1, b2, b3;
            ldsm_x4(b0, b1, b2, b3, baddr + soff + p * 768u);
#pragma unroll
            for (int mf = 0; mf < 2; mf++) {
                mma_f16(acc[mf][2 * p],     a[mf], b0, b1);
                mma_f16(acc[mf][2 * p + 1], a[mf], b2, b3);
            }
        }
    }
#undef ISSUE

    // ---- store C (half2-packed) ----
    const int NP = N >> 1;
#pragma unroll
    for (int mf = 0; mf < 2; mf++) {
#pragma unroll
        for (int nf = 0; nf < 8; nf++) {
            int r = row0 + wm + mf * 16 + (lane >> 2);
            int c = col0 + wn + nf * 8 + (lane & 3) * 2;
            if (c < N) {
                if (r < M)
                    C[(size_t)r * NP + (c >> 1)] = hpk2(acc[mf][nf][0], acc[mf][nf][1]);
                if (r + 8 < M)
                    C[(size_t)(r + 8) * NP + (c >> 1)] = hpk2(acc[mf][nf][2], acc[mf][nf][3]);
            }
        }
    }

    // ---- fused attention scores (fp32 accumulators) ----
    if (col0 + wn < N) {
        const int Hh = N >> 6;
        const int head = (col0 + wn) >> 6;
        float ss[4] = {0.f, 0.f, 0.f, 0.f};
        float sd[4] = {0.f, 0.f, 0.f, 0.f};
#pragma unroll
        for (int nf = 0; nf < 8; nf++) {
            int c = col0 + wn + nf * 8 + (lane & 3) * 2;
            float a0s = aw_s[c], a1s = aw_s[c + 1];
            float a0d = aw_d[c], a1d = aw_d[c + 1];
#pragma unroll
            for (int mf = 0; mf < 2; mf++) {
                ss[mf * 2 + 0] += acc[mf][nf][0] * a0s + acc[mf][nf][1] * a1s;
                ss[mf * 2 + 1] += acc[mf][nf][2] * a0s + acc[mf][nf][3] * a1s;
                sd[mf * 2 + 0] += acc[mf][nf][0] * a0d + acc[mf][nf][1] * a1d;
                sd[mf * 2 + 1] += acc[mf][nf][2] * a0d + acc[mf][nf][3] * a1d;
            }
        }
#pragma unroll
        for (int i = 0; i < 4; i++) {
            ss[i] += __shfl_xor_sync(0xffffffffu, ss[i], 1);
            ss[i] += __shfl_xor_sync(0xffffffffu, ss[i], 2);
            sd[i] += __shfl_xor_sync(0xffffffffu, sd[i], 1);
            sd[i] += __shfl_xor_sync(0xffffffffu, sd[i], 2);
        }
        if ((lane & 3) == 0) {
#pragma unroll
            for (int i = 0; i < 4; i++) {
                int mf = i >> 1, half = i & 1;
                int r = row0 + wm + mf * 16 + half * 8 + (lane >> 2);
                if (r < M) {
                    g_as[r * Hh + head] = ss[i];
                    g_ad[r * Hh + head] = sd[i];
                }
            }
        }
    }
}

// ---------------- GAT aggregation + bias + ELU + BN(eval) ---------------------
// fp16 gather via uint4 (8 feats/thread), 4-way edge split; fp16 activation out.
template <int H, bool POOL>
__global__ void k_agg(const unsigned* __restrict__ h,
                      const float* __restrict__ bias,
                      const float* __restrict__ gamma,
                      const float* __restrict__ beta,
                      unsigned* __restrict__ ah,
                      const int* __restrict__ batch) {
    constexpr int F = H * 64;
    constexpr int FP = F / 2;       // packed u32 per row
    constexpr int T = 32 * H;       // blockDim
    constexpr int CH = 128;
    __shared__ float s_m[H], s_ad[H], s_sum[H];
    __shared__ alignas(16) float s_alpha[CH * H];
    __shared__ int   s_src[CH];
    __shared__ alignas(16) float s_comb[3 * F];
    int n = blockIdx.x;
    int tid = threadIdx.x;
    int row = g_rowptr[n];
    int deg = g_rowptr[n + 1] - row;
    int total = deg + 1;  // + self loop
    if (tid < H) {
        s_ad[tid] = g_ad[n * H + tid];
        s_sum[tid] = 0.f;
    }
    __syncthreads();

    // pass 1: per-head max, one warp per head
    {
        const int w = tid >> 5;
        const int lane = tid & 31;
        const float adw = s_ad[w];
        float mx = -3.0e38f;
        for (int i = lane; i < total; i += 32) {
            int src = (i < deg) ? g_col[row + i] : n;
            float e = g_as[src * H + w] + adw;
            e = e > 0.f ? e : 0.2f * e;
            mx = fmaxf(mx, e);
        }
#pragma unroll
        for (int o = 16; o; o >>= 1) mx = fmaxf(mx, __shfl_xor_sync(0xffffffffu, mx, o));
        if (lane == 0) s_m[w] = mx;
    }
    __syncthreads();

    const int hx = tid & (H - 1);
    const float ad_x = s_ad[hx];
    const float m_x = s_m[hx];
    float psum = 0.f;

    const int f = (tid & (T / 4 - 1)) * 8;   // 8 features per thread
    const int eo = tid / (T / 4);            // 0..3 edge-parity group
    const int hh = f >> 6;
    float a8[8];
#pragma unroll
    for (int j = 0; j < 8; j++) a8[j] = 0.f;

    for (int c0 = 0; c0 < total; c0 += CH) {
        int cn = min(CH, total - c0);
        for (int idx = tid; idx < cn; idx += T) {
            int i = c0 + idx;
            s_src[idx] = (i < deg) ? g_col[row + i] : n;
        }
        __syncthreads();
        for (int idx = tid; idx < cn * H; idx += T) {
            int i = idx / H;
            int src = s_src[i];
            float e = g_as[src * H + hx] + ad_x;
            e = e > 0.f ? e : 0.2f * e;
            float p = __expf(e - m_x);
            s_alpha[idx] = p;
            psum += p;
        }
        __syncthreads();
        for (int i = eo; i < cn; i += 4) {
            int src = s_src[i];
            float al = s_alpha[i * H + hh];
            uint4 v = *(const uint4*)(h + (size_t)src * FP + (f >> 1));
            float2 p0 = __half22float2(*(half2*)&v.x);
            float2 p1 = __half22float2(*(half2*)&v.y);
            float2 p2 = __half22float2(*(half2*)&v.z);
            float2 p3 = __half22float2(*(half2*)&v.w);
            a8[0] += al * p0.x; a8[1] += al * p0.y;
            a8[2] += al * p1.x; a8[3] += al * p1.y;
            a8[4] += al * p2.x; a8[5] += al * p2.y;
            a8[6] += al * p3.x; a8[7] += al * p3.y;
        }
        __syncthreads();
    }

#pragma unroll
    for (int o = H; o < 32; o <<= 1) psum += __shfl_xor_sync(0xffffffffu, psum, o);
    if ((tid & 31) < H) atomicAdd(&s_sum[tid & 31], psum);

    if (eo > 0) {
        *(float4*)&s_comb[(eo - 1) * F + f]     = *(float4*)&a8[0];
        *(float4*)&s_comb[(eo - 1) * F + f + 4] = *(float4*)&a8[4];
    }
    __syncthreads();
    if (eo == 0) {
#pragma unroll
        for (int q = 0; q < 3; q++) {
#pragma unroll
            for (int j = 0; j < 8; j++) a8[j] += s_comb[q * F + f + j];
        }
        float inv = 1.f / (s_sum[hh] + 1e-16f);
        const float inv_std = rsqrtf(1.f + 1e-5f);
        float y[8];
#pragma unroll
        for (int j = 0; j < 8; j++) {
            float v = a8[j] * inv + bias[f + j];
            v = v > 0.f ? v : (__expf(v) - 1.f);
            y[j] = v * (gamma[f + j] * inv_std) + beta[f + j];
        }
        if (POOL) {
            int g = batch[n];
#pragma unroll
            for (int j = 0; j < 8; j++) {
                atomicAdd(&g_gsum[g * 64 + f + j], y[j]);
                atomicMax(&g_gmax[g * 64 + f + j], fenc(y[j]));
            }
            if (tid == 0) atomicAdd(&g_gcnt[g], 1);
        } else {
            *(uint4*)&ah[(size_t)n * FP + (f >> 1)] =
                make_uint4(hpk2(y[0], y[1]), hpk2(y[2], y[3]),
                           hpk2(y[4], y[5]), hpk2(y[6], y[7]));
        }
    }
}

// ---------------- classifier MLP + log_softmax --------------------------------
__global__ void k_mlp(const float* __restrict__ Wc1, const float* __restrict__ bc1,
                      const float* __restrict__ Wc2, const float* __restrict__ bc2,
                      const float* __restrict__ Wc3, const float* __restrict__ bc3,
                      float* __restrict__ outp) {
    int g = blockIdx.x;
    int t = threadIdx.x;  // 128
    __shared__ float z[128];
    __shared__ float h1[64];
    __shared__ float h2[32];
    __shared__ float lg[2];
    int cnt = g_gcnt[g];
    if (t < 64) {
        float mean = g_gsum[g * 64 + t] / fmaxf((float)cnt, 1.f);
        float mx = (cnt == 0) ? 0.f : fdec(g_gmax[g * 64 + t]);
        z[t] = mean;
        z[64 + t] = mx;
    }
    __syncthreads();
    if (t < 64) {
        float acc = bc1[t];
        for (int k = 0; k < 128; k++) acc += z[k] * Wc1[k * 64 + t];
        h1[t] = fmaxf(acc, 0.f);
    }
    __syncthreads();
    if (t < 32) {
        float acc = bc2[t];
        for (int k = 0; k < 64; k++) acc += h1[k] * Wc2[k * 32 + t];
        h2[t] = fmaxf(acc, 0.f);
    }
    __syncthreads();
    if (t < 2) {
        float acc = bc3[t];
        for (int k = 0; k < 32; k++) acc += h2[k] * Wc3[k * 2 + t];
        lg[t] = acc;
    }
    __syncthreads();
    if (t < 2) {
        float m = fmaxf(lg[0], lg[1]);
        float lse = m + logf(expf(lg[0] - m) + expf(lg[1] - m));
        outp[g * 2 + t] = lg[t] - lse;
    }
}

// ---------------- launch ------------------------------------------------------
extern "C" void kernel_launch(void* const* d_in, const int* in_sizes, int n_in,
                              void* d_out, int out_size) {
    const float* x     = (const float*)d_in[0];
    const int*   ei    = (const int*)d_in[1];
    const int*   batch = (const int*)d_in[2];
    const float* W1 = (const float*)d_in[3];
    const float* a1s = (const float*)d_in[4];
    const float* a1d = (const float*)d_in[5];
    const float* b1 = (const float*)d_in[6];
    const float* gm1 = (const float*)d_in[7];
    const float* be1 = (const float*)d_in[8];
    const float* W2 = (const float*)d_in[9];
    const float* a2s = (const float*)d_in[10];
    const float* a2d = (const float*)d_in[11];
    const float* b2 = (const float*)d_in[12];
    const float* gm2 = (const float*)d_in[13];
    const float* be2 = (const float*)d_in[14];
    const float* W3 = (const float*)d_in[15];
    const float* a3s = (const float*)d_in[16];
    const float* a3d = (const float*)d_in[17];
    const float* b3 = (const float*)d_in[18];
    const float* gm3 = (const float*)d_in[19];
    const float* be3 = (const float*)d_in[20];
    const float* Wc1 = (const float*)d_in[21];
    const float* bc1 = (const float*)d_in[22];
    const float* Wc2 = (const float*)d_in[23];
    const float* bc2 = (const float*)d_in[24];
    const float* Wc3 = (const float*)d_in[25];
    const float* bc3 = (const float*)d_in[26];
    float* outp = (float*)d_out;

    const int* esrc = ei;
    const int* edst = ei + EE;

    void* p;
    cudaGetSymbolAddress(&p, g_h);
    unsigned* hbuf = (unsigned*)p;
    cudaGetSymbolAddress(&p, g_ah);
    unsigned* ah = (unsigned*)p;
    cudaGetSymbolAddress(&p, g_wt);
    unsigned* wt = (unsigned*)p;

    const int dynBytes = 2 * NSTAGE * STAGE_U32 * 4;  // 49152
    static bool inited = false;
    static cudaStream_t s2;
    static cudaEvent_t evF, evJ;
    if (!inited) {
        cudaFuncSetAttribute(k_gemm_tc,
                             cudaFuncAttributeMaxDynamicSharedMemorySize, dynBytes);
        cudaStreamCreateWithFlags(&s2, cudaStreamNonBlocking);
        cudaEventCreateWithFlags(&evF, cudaEventDisableTiming);
        cudaEventCreateWithFlags(&evJ, cudaEventDisableTiming);
        inited = true;
    }

    // prep(0): fp16 x + weights, zero counters (CSR count depends on this)
    const int prepTotal = NPX + NW1 + NW2 + NW3;
    k_prep<<<(prepTotal + 255) / 256, 256>>>(x, W1, W2, W3);

    // fork: CSR build on s2, overlapping GEMM1 on the main stream
    cudaEventRecord(evF, 0);
    cudaStreamWaitEvent(s2, evF, 0);
    k_count<<<(EE + 255) / 256, 256, 0, s2>>>(edst);
    k_scan<<<1, 1024, 0, s2>>>();
    {
        dim3 grid(4, (NN + BM - 1) / BM);   // main stream (profiler slot 3)
        k_gemm_tc<<<grid, 256, dynBytes>>>(ah, wt + OFF1, hbuf, a1s, a1d,
                                           NN, 512, 128);
    }
    k_scatter<<<(EE + 255) / 256, 256, 0, s2>>>(esrc, edst);
    cudaEventRecord(evJ, s2);
    cudaStreamWaitEvent(0, evJ, 0);   // join before aggregation

    // ---- layer 1 aggregation (writes fp16 activations for layer 2)
    k_agg<8, false><<<NN, 256>>>(hbuf, b1, gm1, be1, ah, batch);
    // ---- layer 2
    {
        dim3 grid(2, (NN + BM - 1) / BM);
        k_gemm_tc<<<grid, 256, dynBytes>>>(ah, wt + OFF2, hbuf, a2s, a2d,
                                           NN, 256, 512);
        k_agg<4, false><<<NN, 128>>>(hbuf, b2, gm2, be2, ah, batch);
    }
    // ---- layer 3 (pooling fused)
    {
        dim3 grid(1, (NN + BM - 1) / BM);
        k_gemm_tc<<<grid, 256, dynBytes>>>(ah, wt + OFF3, hbuf, a3s, a3d,
                                           NN, 64, 256);
        k_agg<1, true><<<NN, 32>>>(hbuf, b3, gm3, be3, ah, batch);
    }
    // ---- classifier
    k_mlp<<<GG, 128>>>(Wc1, bc1, Wc2, bc2, Wc3, bc3, outp);
}

// round 16
// speedup vs baseline: 1.1896x; 1.1896x over previous
#include <cuda_runtime.h>
#include <cuda_fp16.h>
#include <math.h>

#define NN 30000
#define EE 480000
#define GG 512
#define NSCB 30   // scan blocks (30*1024 >= NN)

// pair counts / weight offsets
#define NPX (NN * 64)          // x pairs (K=128)
#define NW1 (512 * 64)         // W1T pairs: N=512, KP=64
#define NW2 (256 * 256)        // W2T pairs: N=256, KP=256
#define NW3 (64 * 128)         // W3T pairs: N=64,  KP=128
#define OFF1 0
#define OFF2 (NW1)
#define OFF3 (NW1 + NW2)

// ---------------- scratch (static device globals; no allocation) ------------
__device__ unsigned g_h[(size_t)NN * 256];     // GEMM output, half2-packed
__device__ unsigned g_ah[(size_t)NN * 256];    // activations, fp16x2 single plane
__device__ unsigned g_wt[NW1 + NW2 + NW3];     // weights(T), fp16x2 single plane
__device__ float g_as[NN * 8];
__device__ float g_ad[NN * 8];
__device__ int   g_cnt[NN];
__device__ int   g_rowptr[NN + 1];
__device__ int   g_cur[NN];
__device__ int   g_col[EE];
__device__ int   g_bsum[NSCB];
__device__ float g_gsum[GG * 64];
__device__ unsigned g_gmax[GG * 64];
__device__ int   g_gcnt[GG];

// ---------------- helpers ----------------------------------------------------
__device__ __forceinline__ unsigned fenc(float f) {
    unsigned b = __float_as_uint(f);
    return (b & 0x80000000u) ? ~b : (b | 0x80000000u);
}
__device__ __forceinline__ float fdec(unsigned u) {
    return __uint_as_float((u & 0x80000000u) ? (u & 0x7fffffffu) : ~u);
}
__device__ __forceinline__ unsigned hpk2(float x, float y) {
    half2 v = __floats2half2_rn(x, y);
    return *(unsigned*)&v;
}
__device__ __forceinline__ void mma_f16(float c[4], const unsigned a[4],
                                        unsigned b0, unsigned b1) {
    asm volatile(
        "mma.sync.aligned.m16n8k16.row.col.f32.f16.f16.f32 "
        "{%0,%1,%2,%3}, {%4,%5,%6,%7}, {%8,%9}, {%0,%1,%2,%3};"
        : "+f"(c[0]), "+f"(c[1]), "+f"(c[2]), "+f"(c[3])
        : "r"(a[0]), "r"(a[1]), "r"(a[2]), "r"(a[3]), "r"(b0), "r"(b1));
}
__device__ __forceinline__ void ldsm_x4(unsigned& r0, unsigned& r1,
                                        unsigned& r2, unsigned& r3, unsigned addr) {
    asm volatile(
        "ldmatrix.sync.aligned.m8n8.x4.shared.b16 {%0,%1,%2,%3}, [%4];"
        : "=r"(r0), "=r"(r1), "=r"(r2), "=r"(r3) : "r"(addr));
}
__device__ __forceinline__ void cp_async16(unsigned dst, const void* src, int sz) {
    asm volatile("cp.async.cg.shared.global [%0], [%1], 16, %2;"
                 :: "r"(dst), "l"(src), "r"(sz) : "memory");
}
__device__ __forceinline__ void cp_commit() {
    asm volatile("cp.async.commit_group;" ::: "memory");
}
__device__ __forceinline__ void cp_wait2() {
    asm volatile("cp.async.wait_group 2;" ::: "memory");
}

// ---------------- prep: fp16 x + fp16 weights(T), zero counters ---------------
__global__ void k_prep(const float* __restrict__ x,
                       const float* __restrict__ W1,
                       const float* __restrict__ W2,
                       const float* __restrict__ W3) {
    int i = blockIdx.x * blockDim.x + threadIdx.x;
    if (i < NN) g_cnt[i] = 0;
    if (i < GG * 64) {
        g_gsum[i] = 0.f;
        g_gmax[i] = 0x007FFFFFu;  // fenc(-inf)
    }
    if (i < GG) g_gcnt[i] = 0;
    if (i < NPX) {
        float2 v = *(const float2*)(x + 2 * (size_t)i);
        g_ah[i] = hpk2(v.x, v.y);
    } else {
        int j = i - NPX;
        if (j < NW1) {
            int n = j >> 6, kp = j & 63;
            g_wt[OFF1 + n * 64 + kp] =
                hpk2(W1[(2 * kp) * 512 + n], W1[(2 * kp + 1) * 512 + n]);
        } else if ((j -= NW1) < NW2) {
            int n = j >> 8, kp = j & 255;
            g_wt[OFF2 + n * 256 + kp] =
                hpk2(W2[(2 * kp) * 256 + n], W2[(2 * kp + 1) * 256 + n]);
        } else if ((j -= NW2) < NW3) {
            int n = j >> 7, kp = j & 127;
            g_wt[OFF3 + n * 128 + kp] =
                hpk2(W3[(2 * kp) * 64 + n], W3[(2 * kp + 1) * 64 + n]);
        }
    }
}

// ---------------- CSR build (two-level parallel scan) -------------------------
__global__ void k_count(const int* __restrict__ dst) {
    int e = blockIdx.x * blockDim.x + threadIdx.x;
    if (e < EE) atomicAdd(&g_cnt[dst[e]], 1);
}
// stage 1: per-block scan of 1024 counts; partial exclusive into rowptr,
// block total into g_bsum
__global__ void k_scan1() {
    __shared__ int wsum[32];
    int b = blockIdx.x;
    int t = threadIdx.x;
    int lane = t & 31, wid = t >> 5;
    int i = b * 1024 + t;
    int v = (i < NN) ? g_cnt[i] : 0;
    int x = v;
#pragma unroll
    for (int o = 1; o < 32; o <<= 1) {
        int u = __shfl_up_sync(0xffffffffu, x, o);
        if (lane >= o) x += u;
    }
    if (lane == 31) wsum[wid] = x;
    __syncthreads();
    if (wid == 0) {
        int s = wsum[lane];
#pragma unroll
        for (int o = 1; o < 32; o <<= 1) {
            int u = __shfl_up_sync(0xffffffffu, s, o);
            if (lane >= o) s += u;
        }
        wsum[lane] = s;
    }
    __syncthreads();
    int woff = (wid == 0) ? 0 : wsum[wid - 1];
    if (i < NN) g_rowptr[i] = woff + x - v;  // exclusive within block
    if (t == 0) g_bsum[b] = wsum[31];
}
// stage 2: exclusive scan of 30 block sums (one warp)
__global__ void k_scan2() {
    int lane = threadIdx.x;
    int s = (lane < NSCB) ? g_bsum[lane] : 0;
    int inc = s;
#pragma unroll
    for (int o = 1; o < 32; o <<= 1) {
        int u = __shfl_up_sync(0xffffffffu, inc, o);
        if (lane >= o) inc += u;
    }
    if (lane < NSCB) g_bsum[lane] = inc - s;  // exclusive
    if (lane == NSCB - 1) g_rowptr[NN] = inc; // total
}
// stage 3: apply block offsets; init cursor
__global__ void k_scan3() {
    int b = blockIdx.x;
    int i = b * 1024 + threadIdx.x;
    if (i < NN) {
        int r = g_rowptr[i] + g_bsum[b];
        g_rowptr[i] = r;
        g_cur[i] = r;
    }
}
__global__ void k_scatter(const int* __restrict__ src, const int* __restrict__ dst) {
    int e = blockIdx.x * blockDim.x + threadIdx.x;
    if (e < EE) {
        int p = atomicAdd(&g_cur[dst[e]], 1);
        g_col[p] = src[e];
    }
}

// ---------------- single-pass fp16 GEMM, cp.async 4-stage --------------------
#define BM 128
#define BN 128
#define BK 16
#define NSTAGE 4
#define STAGE_U32 1536
#define STAGE_BYTES (STAGE_U32 * 4)

__global__ __launch_bounds__(256, 2) void k_gemm_tc(const unsigned* __restrict__ A,
                                                    const unsigned* __restrict__ Bt,
                                                    unsigned* __restrict__ C,
                                                    const float* __restrict__ aw_s,
                                                    const float* __restrict__ aw_d,
                                                    int M, int N, int K) {
    extern __shared__ __align__(16) unsigned dynsmem[];
    unsigned* As  = dynsmem;                         // [NSTAGE][128][12]
    unsigned* Bts = dynsmem + NSTAGE * STAGE_U32;

    const int tid = threadIdx.x;
    const int lane = tid & 31;
    const int warp = tid >> 5;
    const int wm = (warp >> 1) * 32;
    const int wn = (warp & 1) * 64;
    const int row0 = blockIdx.y * BM;
    const int col0 = blockIdx.x * BN;
    const int KP = K >> 1;

    float acc[2][8][4];
#pragma unroll
    for (int mf = 0; mf < 2; mf++)
#pragma unroll
        for (int nf = 0; nf < 8; nf++)
#pragma unroll
            for (int r = 0; r < 4; r++) acc[mf][nf][r] = 0.f;

    const int ar = tid >> 1;
    const int au0 = (tid & 1) * 4;
    const int agr = row0 + ar;
    const bool aok = (agr < M);
    const int asz = aok ? 16 : 0;
    const int colB = tid & 127;
    const int kpg = (tid >> 7) * 4;
    const int bgc = col0 + colB;
    const bool bok = (bgc < N);
    const int bsz = bok ? 16 : 0;

    const unsigned* a_src = A  + (size_t)(aok ? agr : 0) * KP + au0;
    const unsigned* b_src = Bt + (size_t)(bok ? bgc : 0) * KP + kpg;

    const unsigned d_a = (unsigned)__cvta_generic_to_shared(&As[ar * 12 + au0]);
    const unsigned d_b = (unsigned)__cvta_generic_to_shared(&Bts[colB * 12 + kpg]);

#define ISSUE(s, kb)                                              \
    do {                                                          \
        unsigned o = (unsigned)(s) * STAGE_BYTES;                 \
        cp_async16(d_a + o, a_src + (kb), asz);                   \
        cp_async16(d_b + o, b_src + (kb), bsz);                   \
    } while (0)

    const int arow = ((lane >> 3) & 1) * 8 + (lane & 7);
    const int aucol = (lane >> 4) * 4;
    unsigned aaddr[2];
#pragma unroll
    for (int mf = 0; mf < 2; mf++)
        aaddr[mf] = (unsigned)__cvta_generic_to_shared(
            &As[(wm + mf * 16 + arow) * 12 + aucol]);
    const int bcol = ((lane >> 4) & 1) * 8 + (lane & 7);
    const int bucol = ((lane >> 3) & 1) * 4;
    unsigned baddr = (unsigned)__cvta_generic_to_shared(&Bts[(wn + bcol) * 12 + bucol]);

    const int nIter = K / BK;
    ISSUE(0, 0);
    cp_commit();
    ISSUE(1, 8);
    cp_commit();

    for (int it = 0; it < nIter; it++) {
        if (it + 2 < nIter) ISSUE((it + 2) & 3, (it + 2) * 8);
        cp_commit();
        cp_wait2();
        __syncthreads();

        const unsigned soff = (unsigned)(it & 3) * STAGE_BYTES;
        unsigned a[2][4];
#pragma unroll
        for (int mf = 0; mf < 2; mf++)
            ldsm_x4(a[mf][0], a[mf][1], a[mf][2], a[mf][3], aaddr[mf] + soff);
#pragma unroll
        for (int p = 0; p < 4; p++) {
            unsigned b0, b1, b2, b3;
            ldsm_x4(b0, b1, b2, b3, baddr + soff + p * 768u);
#pragma unroll
            for (int mf = 0; mf < 2; mf++) {
                mma_f16(acc[mf][2 * p],     a[mf], b0, b1);
                mma_f16(acc[mf][2 * p + 1], a[mf], b2, b3);
            }
        }
    }
#undef ISSUE

    // ---- store C (half2-packed) ----
    const int NP = N >> 1;
#pragma unroll
    for (int mf = 0; mf < 2; mf++) {
#pragma unroll
        for (int nf = 0; nf < 8; nf++) {
            int r = row0 + wm + mf * 16 + (lane >> 2);
            int c = col0 + wn + nf * 8 + (lane & 3) * 2;
            if (c < N) {
                if (r < M)
                    C[(size_t)r * NP + (c >> 1)] = hpk2(acc[mf][nf][0], acc[mf][nf][1]);
                if (r + 8 < M)
                    C[(size_t)(r + 8) * NP + (c >> 1)] = hpk2(acc[mf][nf][2], acc[mf][nf][3]);
            }
        }
    }

    // ---- fused attention scores (fp32 accumulators) ----
    if (col0 + wn < N) {
        const int Hh = N >> 6;
        const int head = (col0 + wn) >> 6;
        float ss[4] = {0.f, 0.f, 0.f, 0.f};
        float sd[4] = {0.f, 0.f, 0.f, 0.f};
#pragma unroll
        for (int nf = 0; nf < 8; nf++) {
            int c = col0 + wn + nf * 8 + (lane & 3) * 2;
            float a0s = aw_s[c], a1s = aw_s[c + 1];
            float a0d = aw_d[c], a1d = aw_d[c + 1];
#pragma unroll
            for (int mf = 0; mf < 2; mf++) {
                ss[mf * 2 + 0] += acc[mf][nf][0] * a0s + acc[mf][nf][1] * a1s;
                ss[mf * 2 + 1] += acc[mf][nf][2] * a0s + acc[mf][nf][3] * a1s;
                sd[mf * 2 + 0] += acc[mf][nf][0] * a0d + acc[mf][nf][1] * a1d;
                sd[mf * 2 + 1] += acc[mf][nf][2] * a0d + acc[mf][nf][3] * a1d;
            }
        }
#pragma unroll
        for (int i = 0; i < 4; i++) {
            ss[i] += __shfl_xor_sync(0xffffffffu, ss[i], 1);
            ss[i] += __shfl_xor_sync(0xffffffffu, ss[i], 2);
            sd[i] += __shfl_xor_sync(0xffffffffu, sd[i], 1);
            sd[i] += __shfl_xor_sync(0xffffffffu, sd[i], 2);
        }
        if ((lane & 3) == 0) {
#pragma unroll
            for (int i = 0; i < 4; i++) {
                int mf = i >> 1, half = i & 1;
                int r = row0 + wm + mf * 16 + half * 8 + (lane >> 2);
                if (r < M) {
                    g_as[r * Hh + head] = ss[i];
                    g_ad[r * Hh + head] = sd[i];
                }
            }
        }
    }
}

// ---------------- GAT aggregation + bias + ELU + BN(eval) ---------------------
// r14-proven version: fp16 uint2 gather, 2-way edge split, parallel max pass.
template <int H, bool POOL>
__global__ void k_agg(const unsigned* __restrict__ h,
                      const float* __restrict__ bias,
                      const float* __restrict__ gamma,
                      const float* __restrict__ beta,
                      unsigned* __restrict__ ah,
                      const int* __restrict__ batch) {
    constexpr int F = H * 64;
    constexpr int FP = F / 2;       // packed u32 per row
    constexpr int T = 32 * H;       // blockDim
    constexpr int CH = 128;
    __shared__ float s_m[H], s_ad[H], s_sum[H];
    __shared__ alignas(16) float s_alpha[CH * H];
    __shared__ int   s_src[CH];
    __shared__ alignas(16) float s_comb[F];
    int n = blockIdx.x;
    int tid = threadIdx.x;
    int row = g_rowptr[n];
    int deg = g_rowptr[n + 1] - row;
    int total = deg + 1;  // + self loop
    if (tid < H) {
        s_ad[tid] = g_ad[n * H + tid];
        s_sum[tid] = 0.f;
    }
    __syncthreads();

    // pass 1: per-head max, one warp per head
    {
        const int w = tid >> 5;
        const int lane = tid & 31;
        const float adw = s_ad[w];
        float mx = -3.0e38f;
        for (int i = lane; i < total; i += 32) {
            int src = (i < deg) ? g_col[row + i] : n;
            float e = g_as[src * H + w] + adw;
            e = e > 0.f ? e : 0.2f * e;
            mx = fmaxf(mx, e);
        }
#pragma unroll
        for (int o = 16; o; o >>= 1) mx = fmaxf(mx, __shfl_xor_sync(0xffffffffu, mx, o));
        if (lane == 0) s_m[w] = mx;
    }
    __syncthreads();

    const int hx = tid & (H - 1);
    const float ad_x = s_ad[hx];
    const float m_x = s_m[hx];
    float psum = 0.f;

    const int half = tid & (T / 2 - 1);
    const int eo = tid / (T / 2);
    const int f = half * 4;
    const int hh = f >> 6;
    float4 acc = make_float4(0.f, 0.f, 0.f, 0.f);

    for (int c0 = 0; c0 < total; c0 += CH) {
        int cn = min(CH, total - c0);
        for (int idx = tid; idx < cn; idx += T) {
            int i = c0 + idx;
            s_src[idx] = (i < deg) ? g_col[row + i] : n;
        }
        __syncthreads();
        for (int idx = tid; idx < cn * H; idx += T) {
            int i = idx / H;
            int src = s_src[i];
            float e = g_as[src * H + hx] + ad_x;
            e = e > 0.f ? e : 0.2f * e;
            float p = __expf(e - m_x);
            s_alpha[idx] = p;
            psum += p;
        }
        __syncthreads();
        for (int i = eo; i < cn; i += 2) {
            int src = s_src[i];
            float a = s_alpha[i * H + hh];
            uint2 v = *(const uint2*)(h + (size_t)src * FP + (f >> 1));
            float2 v0 = __half22float2(*(half2*)&v.x);
            float2 v1 = __half22float2(*(half2*)&v.y);
            acc.x += a * v0.x;
            acc.y += a * v0.y;
            acc.z += a * v1.x;
            acc.w += a * v1.y;
        }
        __syncthreads();
    }

#pragma unroll
    for (int o = H; o < 32; o <<= 1) psum += __shfl_xor_sync(0xffffffffu, psum, o);
    if ((tid & 31) < H) atomicAdd(&s_sum[tid & 31], psum);

    if (eo == 1) *(float4*)&s_comb[f] = acc;
    __syncthreads();
    if (eo == 0) {
        float4 o2 = *(float4*)&s_comb[f];
        float inv = 1.f / (s_sum[hh] + 1e-16f);
        const float inv_std = rsqrtf(1.f + 1e-5f);
        float y[4] = {(acc.x + o2.x) * inv, (acc.y + o2.y) * inv,
                      (acc.z + o2.z) * inv, (acc.w + o2.w) * inv};
#pragma unroll
        for (int j = 0; j < 4; j++) {
            float v = y[j] + bias[f + j];
            v = v > 0.f ? v : (__expf(v) - 1.f);
            y[j] = v * (gamma[f + j] * inv_std) + beta[f + j];
        }
        if (POOL) {
            int g = batch[n];
#pragma unroll
            for (int j = 0; j < 4; j++) {
                atomicAdd(&g_gsum[g * 64 + f + j], y[j]);
                atomicMax(&g_gmax[g * 64 + f + j], fenc(y[j]));
            }
            if (tid == 0) atomicAdd(&g_gcnt[g], 1);
        } else {
            *(uint2*)&ah[(size_t)n * FP + (f >> 1)] =
                make_uint2(hpk2(y[0], y[1]), hpk2(y[2], y[3]));
        }
    }
}

// ---------------- classifier MLP + log_softmax --------------------------------
__global__ void k_mlp(const float* __restrict__ Wc1, const float* __restrict__ bc1,
                      const float* __restrict__ Wc2, const float* __restrict__ bc2,
                      const float* __restrict__ Wc3, const float* __restrict__ bc3,
                      float* __restrict__ outp) {
    int g = blockIdx.x;
    int t = threadIdx.x;  // 128
    __shared__ float z[128];
    __shared__ float h1[64];
    __shared__ float h2[32];
    __shared__ float lg[2];
    int cnt = g_gcnt[g];
    if (t < 64) {
        float mean = g_gsum[g * 64 + t] / fmaxf((float)cnt, 1.f);
        float mx = (cnt == 0) ? 0.f : fdec(g_gmax[g * 64 + t]);
        z[t] = mean;
        z[64 + t] = mx;
    }
    __syncthreads();
    if (t < 64) {
        float acc = bc1[t];
        for (int k = 0; k < 128; k++) acc += z[k] * Wc1[k * 64 + t];
        h1[t] = fmaxf(acc, 0.f);
    }
    __syncthreads();
    if (t < 32) {
        float acc = bc2[t];
        for (int k = 0; k < 64; k++) acc += h1[k] * Wc2[k * 32 + t];
        h2[t] = fmaxf(acc, 0.f);
    }
    __syncthreads();
    if (t < 2) {
        float acc = bc3[t];
        for (int k = 0; k < 32; k++) acc += h2[k] * Wc3[k * 2 + t];
        lg[t] = acc;
    }
    __syncthreads();
    if (t < 2) {
        float m = fmaxf(lg[0], lg[1]);
        float lse = m + logf(expf(lg[0] - m) + expf(lg[1] - m));
        outp[g * 2 + t] = lg[t] - lse;
    }
}

// ---------------- launch ------------------------------------------------------
extern "C" void kernel_launch(void* const* d_in, const int* in_sizes, int n_in,
                              void* d_out, int out_size) {
    const float* x     = (const float*)d_in[0];
    const int*   ei    = (const int*)d_in[1];
    const int*   batch = (const int*)d_in[2];
    const float* W1 = (const float*)d_in[3];
    const float* a1s = (const float*)d_in[4];
    const float* a1d = (const float*)d_in[5];
    const float* b1 = (const float*)d_in[6];
    const float* gm1 = (const float*)d_in[7];
    const float* be1 = (const float*)d_in[8];
    const float* W2 = (const float*)d_in[9];
    const float* a2s = (const float*)d_in[10];
    const float* a2d = (const float*)d_in[11];
    const float* b2 = (const float*)d_in[12];
    const float* gm2 = (const float*)d_in[13];
    const float* be2 = (const float*)d_in[14];
    const float* W3 = (const float*)d_in[15];
    const float* a3s = (const float*)d_in[16];
    const float* a3d = (const float*)d_in[17];
    const float* b3 = (const float*)d_in[18];
    const float* gm3 = (const float*)d_in[19];
    const float* be3 = (const float*)d_in[20];
    const float* Wc1 = (const float*)d_in[21];
    const float* bc1 = (const float*)d_in[22];
    const float* Wc2 = (const float*)d_in[23];
    const float* bc2 = (const float*)d_in[24];
    const float* Wc3 = (const float*)d_in[25];
    const float* bc3 = (const float*)d_in[26];
    float* outp = (float*)d_out;

    const int* esrc = ei;
    const int* edst = ei + EE;

    void* p;
    cudaGetSymbolAddress(&p, g_h);
    unsigned* hbuf = (unsigned*)p;
    cudaGetSymbolAddress(&p, g_ah);
    unsigned* ah = (unsigned*)p;
    cudaGetSymbolAddress(&p, g_wt);
    unsigned* wt = (unsigned*)p;

    const int dynBytes = 2 * NSTAGE * STAGE_U32 * 4;  // 49152
    static bool attrSet = false;
    if (!attrSet) {
        cudaFuncSetAttribute(k_gemm_tc,
                             cudaFuncAttributeMaxDynamicSharedMemorySize, dynBytes);
        attrSet = true;
    }

    // prep(0): fp16 x + weights, zero counters
    const int prepTotal = NPX + NW1 + NW2 + NW3;
    k_prep<<<(prepTotal + 255) / 256, 256>>>(x, W1, W2, W3);
    k_count<<<(EE + 255) / 256, 256>>>(edst);          // 1
    k_scan1<<<NSCB, 1024>>>();                         // 2
    {
        dim3 grid(4, (NN + BM - 1) / BM);              // 3: profiler slot
        k_gemm_tc<<<grid, 256, dynBytes>>>(ah, wt + OFF1, hbuf, a1s, a1d,
                                           NN, 512, 128);
    }
    k_scan2<<<1, 32>>>();                              // 4
    k_scan3<<<NSCB, 1024>>>();                         // 5
    k_scatter<<<(EE + 255) / 256, 256>>>(esrc, edst);  // 6

    // ---- layer 1 aggregation (writes fp16 activations for layer 2)
    k_agg<8, false><<<NN, 256>>>(hbuf, b1, gm1, be1, ah, batch);
    // ---- layer 2
    {
        dim3 grid(2, (NN + BM - 1) / BM);
        k_gemm_tc<<<grid, 256, dynBytes>>>(ah, wt + OFF2, hbuf, a2s, a2d,
                                           NN, 256, 512);
        k_agg<4, false><<<NN, 128>>>(hbuf, b2, gm2, be2, ah, batch);
    }
    // ---- layer 3 (pooling fused)
    {
        dim3 grid(1, (NN + BM - 1) / BM);
        k_gemm_tc<<<grid, 256, dynBytes>>>(ah, wt + OFF3, hbuf, a3s, a3d,
                                           NN, 64, 256);
        k_agg<1, true><<<NN, 32>>>(hbuf, b3, gm3, be3, ah, batch);
    }
    // ---- classifier
    k_mlp<<<GG, 128>>>(Wc1, bc1, Wc2, bc2, Wc3, bc3, outp);
}

// round 17
// speedup vs baseline: 1.2141x; 1.0206x over previous
#include <cuda_runtime.h>
#include <cuda_fp16.h>
#include <math.h>

#define NN 30000
#define EE 480000
#define GG 512
#define NSCB 30   // scan blocks (30*1024 >= NN)

// pair counts / weight offsets
#define NPX (NN * 64)          // x pairs (K=128)
#define NW1 (512 * 64)         // W1T pairs: N=512, KP=64
#define NW2 (256 * 256)        // W2T pairs: N=256, KP=256
#define NW3 (64 * 128)         // W3T pairs: N=64,  KP=128
#define OFF1 0
#define OFF2 (NW1)
#define OFF3 (NW1 + NW2)

// ---------------- scratch (static device globals; no allocation) ------------
__device__ unsigned g_h[(size_t)NN * 256];     // GEMM output, half2-packed
__device__ unsigned g_ah[(size_t)NN * 256];    // activations, fp16x2 single plane
__device__ unsigned g_wt[NW1 + NW2 + NW3];     // weights(T), fp16x2 single plane
__device__ float g_as[NN * 8];
__device__ float g_ad[NN * 8];
__device__ int   g_cnt[NN];
__device__ int   g_rowptr[NN + 1];
__device__ int   g_cur[NN];
__device__ int   g_col[EE];
__device__ int   g_bsum[NSCB];
__device__ float g_gsum[GG * 64];
__device__ unsigned g_gmax[GG * 64];
__device__ int   g_gcnt[GG];

// ---------------- helpers ----------------------------------------------------
__device__ __forceinline__ unsigned fenc(float f) {
    unsigned b = __float_as_uint(f);
    return (b & 0x80000000u) ? ~b : (b | 0x80000000u);
}
__device__ __forceinline__ float fdec(unsigned u) {
    return __uint_as_float((u & 0x80000000u) ? (u & 0x7fffffffu) : ~u);
}
__device__ __forceinline__ unsigned hpk2(float x, float y) {
    half2 v = __floats2half2_rn(x, y);
    return *(unsigned*)&v;
}
__device__ __forceinline__ void mma_f16(float c[4], const unsigned a[4],
                                        unsigned b0, unsigned b1) {
    asm volatile(
        "mma.sync.aligned.m16n8k16.row.col.f32.f16.f16.f32 "
        "{%0,%1,%2,%3}, {%4,%5,%6,%7}, {%8,%9}, {%0,%1,%2,%3};"
        : "+f"(c[0]), "+f"(c[1]), "+f"(c[2]), "+f"(c[3])
        : "r"(a[0]), "r"(a[1]), "r"(a[2]), "r"(a[3]), "r"(b0), "r"(b1));
}
__device__ __forceinline__ void ldsm_x4(unsigned& r0, unsigned& r1,
                                        unsigned& r2, unsigned& r3, unsigned addr) {
    asm volatile(
        "ldmatrix.sync.aligned.m8n8.x4.shared.b16 {%0,%1,%2,%3}, [%4];"
        : "=r"(r0), "=r"(r1), "=r"(r2), "=r"(r3) : "r"(addr));
}
__device__ __forceinline__ void cp_async16(unsigned dst, const void* src, int sz) {
    asm volatile("cp.async.cg.shared.global [%0], [%1], 16, %2;"
                 :: "r"(dst), "l"(src), "r"(sz) : "memory");
}
__device__ __forceinline__ void cp_commit() {
    asm volatile("cp.async.commit_group;" ::: "memory");
}
__device__ __forceinline__ void cp_wait2() {
    asm volatile("cp.async.wait_group 2;" ::: "memory");
}

// ---------------- prep: fp16 x + fp16 weights(T), zero counters ---------------
__global__ void k_prep(const float* __restrict__ x,
                       const float* __restrict__ W1,
                       const float* __restrict__ W2,
                       const float* __restrict__ W3) {
    int i = blockIdx.x * blockDim.x + threadIdx.x;
    if (i < NN) g_cnt[i] = 0;
    if (i < GG * 64) {
        g_gsum[i] = 0.f;
        g_gmax[i] = 0x007FFFFFu;  // fenc(-inf)
    }
    if (i < GG) g_gcnt[i] = 0;
    if (i < NPX) {
        float2 v = *(const float2*)(x + 2 * (size_t)i);
        g_ah[i] = hpk2(v.x, v.y);
    } else {
        int j = i - NPX;
        if (j < NW1) {
            int n = j >> 6, kp = j & 63;
            g_wt[OFF1 + n * 64 + kp] =
                hpk2(W1[(2 * kp) * 512 + n], W1[(2 * kp + 1) * 512 + n]);
        } else if ((j -= NW1) < NW2) {
            int n = j >> 8, kp = j & 255;
            g_wt[OFF2 + n * 256 + kp] =
                hpk2(W2[(2 * kp) * 256 + n], W2[(2 * kp + 1) * 256 + n]);
        } else if ((j -= NW2) < NW3) {
            int n = j >> 7, kp = j & 127;
            g_wt[OFF3 + n * 128 + kp] =
                hpk2(W3[(2 * kp) * 64 + n], W3[(2 * kp + 1) * 64 + n]);
        }
    }
}

// ---------------- CSR build (two-level parallel scan) -------------------------
__global__ void k_count(const int* __restrict__ dst) {
    int e = blockIdx.x * blockDim.x + threadIdx.x;
    if (e < EE) atomicAdd(&g_cnt[dst[e]], 1);
}
__global__ void k_scan1() {
    __shared__ int wsum[32];
    int b = blockIdx.x;
    int t = threadIdx.x;
    int lane = t & 31, wid = t >> 5;
    int i = b * 1024 + t;
    int v = (i < NN) ? g_cnt[i] : 0;
    int x = v;
#pragma unroll
    for (int o = 1; o < 32; o <<= 1) {
        int u = __shfl_up_sync(0xffffffffu, x, o);
        if (lane >= o) x += u;
    }
    if (lane == 31) wsum[wid] = x;
    __syncthreads();
    if (wid == 0) {
        int s = wsum[lane];
#pragma unroll
        for (int o = 1; o < 32; o <<= 1) {
            int u = __shfl_up_sync(0xffffffffu, s, o);
            if (lane >= o) s += u;
        }
        wsum[lane] = s;
    }
    __syncthreads();
    int woff = (wid == 0) ? 0 : wsum[wid - 1];
    if (i < NN) g_rowptr[i] = woff + x - v;  // exclusive within block
    if (t == 0) g_bsum[b] = wsum[31];
}
__global__ void k_scan2() {
    int lane = threadIdx.x;
    int s = (lane < NSCB) ? g_bsum[lane] : 0;
    int inc = s;
#pragma unroll
    for (int o = 1; o < 32; o <<= 1) {
        int u = __shfl_up_sync(0xffffffffu, inc, o);
        if (lane >= o) inc += u;
    }
    if (lane < NSCB) g_bsum[lane] = inc - s;  // exclusive
    if (lane == NSCB - 1) g_rowptr[NN] = inc; // total
}
__global__ void k_scan3() {
    int b = blockIdx.x;
    int i = b * 1024 + threadIdx.x;
    if (i < NN) {
        int r = g_rowptr[i] + g_bsum[b];
        g_rowptr[i] = r;
        g_cur[i] = r;
    }
}
__global__ void k_scatter(const int* __restrict__ src, const int* __restrict__ dst) {
    int e = blockIdx.x * blockDim.x + threadIdx.x;
    if (e < EE) {
        int p = atomicAdd(&g_cur[dst[e]], 1);
        g_col[p] = src[e];
    }
}

// ---------------- single-pass fp16 GEMM, cp.async 4-stage --------------------
#define BM 128
#define BN 128
#define BK 16
#define NSTAGE 4
#define STAGE_U32 1536
#define STAGE_BYTES (STAGE_U32 * 4)

__global__ __launch_bounds__(256, 2) void k_gemm_tc(const unsigned* __restrict__ A,
                                                    const unsigned* __restrict__ Bt,
                                                    unsigned* __restrict__ C,
                                                    const float* __restrict__ aw_s,
                                                    const float* __restrict__ aw_d,
                                                    int M, int N, int K) {
    extern __shared__ __align__(16) unsigned dynsmem[];
    unsigned* As  = dynsmem;                         // [NSTAGE][128][12]
    unsigned* Bts = dynsmem + NSTAGE * STAGE_U32;

    const int tid = threadIdx.x;
    const int lane = tid & 31;
    const int warp = tid >> 5;
    const int wm = (warp >> 1) * 32;
    const int wn = (warp & 1) * 64;
    const int row0 = blockIdx.y * BM;
    const int col0 = blockIdx.x * BN;
    const int KP = K >> 1;

    float acc[2][8][4];
#pragma unroll
    for (int mf = 0; mf < 2; mf++)
#pragma unroll
        for (int nf = 0; nf < 8; nf++)
#pragma unroll
            for (int r = 0; r < 4; r++) acc[mf][nf][r] = 0.f;

    const int ar = tid >> 1;
    const int au0 = (tid & 1) * 4;
    const int agr = row0 + ar;
    const bool aok = (agr < M);
    const int asz = aok ? 16 : 0;
    const int colB = tid & 127;
    const int kpg = (tid >> 7) * 4;
    const int bgc = col0 + colB;
    const bool bok = (bgc < N);
    const int bsz = bok ? 16 : 0;

    const unsigned* a_src = A  + (size_t)(aok ? agr : 0) * KP + au0;
    const unsigned* b_src = Bt + (size_t)(bok ? bgc : 0) * KP + kpg;

    const unsigned d_a = (unsigned)__cvta_generic_to_shared(&As[ar * 12 + au0]);
    const unsigned d_b = (unsigned)__cvta_generic_to_shared(&Bts[colB * 12 + kpg]);

#define ISSUE(s, kb)                                              \
    do {                                                          \
        unsigned o = (unsigned)(s) * STAGE_BYTES;                 \
        cp_async16(d_a + o, a_src + (kb), asz);                   \
        cp_async16(d_b + o, b_src + (kb), bsz);                   \
    } while (0)

    const int arow = ((lane >> 3) & 1) * 8 + (lane & 7);
    const int aucol = (lane >> 4) * 4;
    unsigned aaddr[2];
#pragma unroll
    for (int mf = 0; mf < 2; mf++)
        aaddr[mf] = (unsigned)__cvta_generic_to_shared(
            &As[(wm + mf * 16 + arow) * 12 + aucol]);
    const int bcol = ((lane >> 4) & 1) * 8 + (lane & 7);
    const int bucol = ((lane >> 3) & 1) * 4;
    unsigned baddr = (unsigned)__cvta_generic_to_shared(&Bts[(wn + bcol) * 12 + bucol]);

    const int nIter = K / BK;
    ISSUE(0, 0);
    cp_commit();
    ISSUE(1, 8);
    cp_commit();

    for (int it = 0; it < nIter; it++) {
        if (it + 2 < nIter) ISSUE((it + 2) & 3, (it + 2) * 8);
        cp_commit();
        cp_wait2();
        __syncthreads();

        const unsigned soff = (unsigned)(it & 3) * STAGE_BYTES;
        unsigned a[2][4];
#pragma unroll
        for (int mf = 0; mf < 2; mf++)
            ldsm_x4(a[mf][0], a[mf][1], a[mf][2], a[mf][3], aaddr[mf] + soff);
#pragma unroll
        for (int p = 0; p < 4; p++) {
            unsigned b0, b1, b2, b3;
            ldsm_x4(b0, b1, b2, b3, baddr + soff + p * 768u);
#pragma unroll
            for (int mf = 0; mf < 2; mf++) {
                mma_f16(acc[mf][2 * p],     a[mf], b0, b1);
                mma_f16(acc[mf][2 * p + 1], a[mf], b2, b3);
            }
        }
    }
#undef ISSUE

    // ---- store C (half2-packed) ----
    const int NP = N >> 1;
#pragma unroll
    for (int mf = 0; mf < 2; mf++) {
#pragma unroll
        for (int nf = 0; nf < 8; nf++) {
            int r = row0 + wm + mf * 16 + (lane >> 2);
            int c = col0 + wn + nf * 8 + (lane & 3) * 2;
            if (c < N) {
                if (r < M)
                    C[(size_t)r * NP + (c >> 1)] = hpk2(acc[mf][nf][0], acc[mf][nf][1]);
                if (r + 8 < M)
                    C[(size_t)(r + 8) * NP + (c >> 1)] = hpk2(acc[mf][nf][2], acc[mf][nf][3]);
            }
        }
    }

    // ---- fused attention scores (fp32 accumulators) ----
    if (col0 + wn < N) {
        const int Hh = N >> 6;
        const int head = (col0 + wn) >> 6;
        float ss[4] = {0.f, 0.f, 0.f, 0.f};
        float sd[4] = {0.f, 0.f, 0.f, 0.f};
#pragma unroll
        for (int nf = 0; nf < 8; nf++) {
            int c = col0 + wn + nf * 8 + (lane & 3) * 2;
            float a0s = aw_s[c], a1s = aw_s[c + 1];
            float a0d = aw_d[c], a1d = aw_d[c + 1];
#pragma unroll
            for (int mf = 0; mf < 2; mf++) {
                ss[mf * 2 + 0] += acc[mf][nf][0] * a0s + acc[mf][nf][1] * a1s;
                ss[mf * 2 + 1] += acc[mf][nf][2] * a0s + acc[mf][nf][3] * a1s;
                sd[mf * 2 + 0] += acc[mf][nf][0] * a0d + acc[mf][nf][1] * a1d;
                sd[mf * 2 + 1] += acc[mf][nf][2] * a0d + acc[mf][nf][3] * a1d;
            }
        }
#pragma unroll
        for (int i = 0; i < 4; i++) {
            ss[i] += __shfl_xor_sync(0xffffffffu, ss[i], 1);
            ss[i] += __shfl_xor_sync(0xffffffffu, ss[i], 2);
            sd[i] += __shfl_xor_sync(0xffffffffu, sd[i], 1);
            sd[i] += __shfl_xor_sync(0xffffffffu, sd[i], 2);
        }
        if ((lane & 3) == 0) {
#pragma unroll
            for (int i = 0; i < 4; i++) {
                int mf = i >> 1, half = i & 1;
                int r = row0 + wm + mf * 16 + half * 8 + (lane >> 2);
                if (r < M) {
                    g_as[r * Hh + head] = ss[i];
                    g_ad[r * Hh + head] = sd[i];
                }
            }
        }
    }
}

// ---------------- GAT aggregation + bias + ELU + BN(eval) ---------------------
template <int H, bool POOL>
__global__ void k_agg(const unsigned* __restrict__ h,
                      const float* __restrict__ bias,
                      const float* __restrict__ gamma,
                      const float* __restrict__ beta,
                      unsigned* __restrict__ ah,
                      const int* __restrict__ batch) {
    constexpr int F = H * 64;
    constexpr int FP = F / 2;
    constexpr int T = 32 * H;
    constexpr int CH = 128;
    __shared__ float s_m[H], s_ad[H], s_sum[H];
    __shared__ alignas(16) float s_alpha[CH * H];
    __shared__ int   s_src[CH];
    __shared__ alignas(16) float s_comb[F];
    int n = blockIdx.x;
    int tid = threadIdx.x;
    int row = g_rowptr[n];
    int deg = g_rowptr[n + 1] - row;
    int total = deg + 1;
    if (tid < H) {
        s_ad[tid] = g_ad[n * H + tid];
        s_sum[tid] = 0.f;
    }
    __syncthreads();

    {
        const int w = tid >> 5;
        const int lane = tid & 31;
        const float adw = s_ad[w];
        float mx = -3.0e38f;
        for (int i = lane; i < total; i += 32) {
            int src = (i < deg) ? g_col[row + i] : n;
            float e = g_as[src * H + w] + adw;
            e = e > 0.f ? e : 0.2f * e;
            mx = fmaxf(mx, e);
        }
#pragma unroll
        for (int o = 16; o; o >>= 1) mx = fmaxf(mx, __shfl_xor_sync(0xffffffffu, mx, o));
        if (lane == 0) s_m[w] = mx;
    }
    __syncthreads();

    const int hx = tid & (H - 1);
    const float ad_x = s_ad[hx];
    const float m_x = s_m[hx];
    float psum = 0.f;

    const int half = tid & (T / 2 - 1);
    const int eo = tid / (T / 2);
    const int f = half * 4;
    const int hh = f >> 6;
    float4 acc = make_float4(0.f, 0.f, 0.f, 0.f);

    for (int c0 = 0; c0 < total; c0 += CH) {
        int cn = min(CH, total - c0);
        for (int idx = tid; idx < cn; idx += T) {
            int i = c0 + idx;
            s_src[idx] = (i < deg) ? g_col[row + i] : n;
        }
        __syncthreads();
        for (int idx = tid; idx < cn * H; idx += T) {
            int i = idx / H;
            int src = s_src[i];
            float e = g_as[src * H + hx] + ad_x;
            e = e > 0.f ? e : 0.2f * e;
            float p = __expf(e - m_x);
            s_alpha[idx] = p;
            psum += p;
        }
        __syncthreads();
        for (int i = eo; i < cn; i += 2) {
            int src = s_src[i];
            float a = s_alpha[i * H + hh];
            uint2 v = *(const uint2*)(h + (size_t)src * FP + (f >> 1));
            float2 v0 = __half22float2(*(half2*)&v.x);
            float2 v1 = __half22float2(*(half2*)&v.y);
            acc.x += a * v0.x;
            acc.y += a * v0.y;
            acc.z += a * v1.x;
            acc.w += a * v1.y;
        }
        __syncthreads();
    }

#pragma unroll
    for (int o = H; o < 32; o <<= 1) psum += __shfl_xor_sync(0xffffffffu, psum, o);
    if ((tid & 31) < H) atomicAdd(&s_sum[tid & 31], psum);

    if (eo == 1) *(float4*)&s_comb[f] = acc;
    __syncthreads();
    if (eo == 0) {
        float4 o2 = *(float4*)&s_comb[f];
        float inv = 1.f / (s_sum[hh] + 1e-16f);
        const float inv_std = rsqrtf(1.f + 1e-5f);
        float y[4] = {(acc.x + o2.x) * inv, (acc.y + o2.y) * inv,
                      (acc.z + o2.z) * inv, (acc.w + o2.w) * inv};
#pragma unroll
        for (int j = 0; j < 4; j++) {
            float v = y[j] + bias[f + j];
            v = v > 0.f ? v : (__expf(v) - 1.f);
            y[j] = v * (gamma[f + j] * inv_std) + beta[f + j];
        }
        if (POOL) {
            int g = batch[n];
#pragma unroll
            for (int j = 0; j < 4; j++) {
                atomicAdd(&g_gsum[g * 64 + f + j], y[j]);
                atomicMax(&g_gmax[g * 64 + f + j], fenc(y[j]));
            }
            if (tid == 0) atomicAdd(&g_gcnt[g], 1);
        } else {
            *(uint2*)&ah[(size_t)n * FP + (f >> 1)] =
                make_uint2(hpk2(y[0], y[1]), hpk2(y[2], y[3]));
        }
    }
}

// ---------------- classifier MLP + log_softmax --------------------------------
__global__ void k_mlp(const float* __restrict__ Wc1, const float* __restrict__ bc1,
                      const float* __restrict__ Wc2, const float* __restrict__ bc2,
                      const float* __restrict__ Wc3, const float* __restrict__ bc3,
                      float* __restrict__ outp) {
    int g = blockIdx.x;
    int t = threadIdx.x;  // 128
    __shared__ float z[128];
    __shared__ float h1[64];
    __shared__ float h2[32];
    __shared__ float lg[2];
    int cnt = g_gcnt[g];
    if (t < 64) {
        float mean = g_gsum[g * 64 + t] / fmaxf((float)cnt, 1.f);
        float mx = (cnt == 0) ? 0.f : fdec(g_gmax[g * 64 + t]);
        z[t] = mean;
        z[64 + t] = mx;
    }
    __syncthreads();
    if (t < 64) {
        float acc = bc1[t];
        for (int k = 0; k < 128; k++) acc += z[k] * Wc1[k * 64 + t];
        h1[t] = fmaxf(acc, 0.f);
    }
    __syncthreads();
    if (t < 32) {
        float acc = bc2[t];
        for (int k = 0; k < 64; k++) acc += h1[k] * Wc2[k * 32 + t];
        h2[t] = fmaxf(acc, 0.f);
    }
    __syncthreads();
    if (t < 2) {
        float acc = bc3[t];
        for (int k = 0; k < 32; k++) acc += h2[k] * Wc3[k * 2 + t];
        lg[t] = acc;
    }
    __syncthreads();
    if (t < 2) {
        float m = fmaxf(lg[0], lg[1]);
        float lse = m + logf(expf(lg[0] - m) + expf(lg[1] - m));
        outp[g * 2 + t] = lg[t] - lse;
    }
}

// ---------------- launch ------------------------------------------------------
extern "C" void kernel_launch(void* const* d_in, const int* in_sizes, int n_in,
                              void* d_out, int out_size) {
    const float* x     = (const float*)d_in[0];
    const int*   ei    = (const int*)d_in[1];
    const int*   batch = (const int*)d_in[2];
    const float* W1 = (const float*)d_in[3];
    const float* a1s = (const float*)d_in[4];
    const float* a1d = (const float*)d_in[5];
    const float* b1 = (const float*)d_in[6];
    const float* gm1 = (const float*)d_in[7];
    const float* be1 = (const float*)d_in[8];
    const float* W2 = (const float*)d_in[9];
    const float* a2s = (const float*)d_in[10];
    const float* a2d = (const float*)d_in[11];
    const float* b2 = (const float*)d_in[12];
    const float* gm2 = (const float*)d_in[13];
    const float* be2 = (const float*)d_in[14];
    const float* W3 = (const float*)d_in[15];
    const float* a3s = (const float*)d_in[16];
    const float* a3d = (const float*)d_in[17];
    const float* b3 = (const float*)d_in[18];
    const float* gm3 = (const float*)d_in[19];
    const float* be3 = (const float*)d_in[20];
    const float* Wc1 = (const float*)d_in[21];
    const float* bc1 = (const float*)d_in[22];
    const float* Wc2 = (const float*)d_in[23];
    const float* bc2 = (const float*)d_in[24];
    const float* Wc3 = (const float*)d_in[25];
    const float* bc3 = (const float*)d_in[26];
    float* outp = (float*)d_out;

    const int* esrc = ei;
    const int* edst = ei + EE;

    void* p;
    cudaGetSymbolAddress(&p, g_h);
    unsigned* hbuf = (unsigned*)p;
    cudaGetSymbolAddress(&p, g_ah);
    unsigned* ah = (unsigned*)p;
    cudaGetSymbolAddress(&p, g_wt);
    unsigned* wt = (unsigned*)p;

    const int dynBytes = 2 * NSTAGE * STAGE_U32 * 4;  // 49152
    static bool inited = false;
    static cudaStream_t s2;
    static cudaEvent_t evF, evJ;
    if (!inited) {
        cudaFuncSetAttribute(k_gemm_tc,
                             cudaFuncAttributeMaxDynamicSharedMemorySize, dynBytes);
        cudaStreamCreateWithFlags(&s2, cudaStreamNonBlocking);
        cudaEventCreateWithFlags(&evF, cudaEventDisableTiming);
        cudaEventCreateWithFlags(&evJ, cudaEventDisableTiming);
        inited = true;
    }

    // prep(0): fp16 x + weights, zero counters (CSR count depends on this)
    const int prepTotal = NPX + NW1 + NW2 + NW3;
    k_prep<<<(prepTotal + 255) / 256, 256>>>(x, W1, W2, W3);

    // fork: whole CSR chain on s2, overlapping GEMM1 on the main stream
    cudaEventRecord(evF, 0);
    cudaStreamWaitEvent(s2, evF, 0);
    k_count<<<(EE + 255) / 256, 256, 0, s2>>>(edst);
    k_scan1<<<NSCB, 1024, 0, s2>>>();
    {
        dim3 grid(4, (NN + BM - 1) / BM);   // main stream (profiler slot 3)
        k_gemm_tc<<<grid, 256, dynBytes>>>(ah, wt + OFF1, hbuf, a1s, a1d,
                                           NN, 512, 128);
    }
    k_scan2<<<1, 32, 0, s2>>>();
    k_scan3<<<NSCB, 1024, 0, s2>>>();
    k_scatter<<<(EE + 255) / 256, 256, 0, s2>>>(esrc, edst);
    cudaEventRecord(evJ, s2);
    cudaStreamWaitEvent(0, evJ, 0);   // join before aggregation

    // ---- layer 1 aggregation (writes fp16 activations for layer 2)
    k_agg<8, false><<<NN, 256>>>(hbuf, b1, gm1, be1, ah, batch);
    // ---- layer 2
    {
        dim3 grid(2, (NN + BM - 1) / BM);
        k_gemm_tc<<<grid, 256, dynBytes>>>(ah, wt + OFF2, hbuf, a2s, a2d,
                                           NN, 256, 512);
        k_agg<4, false><<<NN, 128>>>(hbuf, b2, gm2, be2, ah, batch);
    }
    // ---- layer 3 (pooling fused)
    {
        dim3 grid(1, (NN + BM - 1) / BM);
        k_gemm_tc<<<grid, 256, dynBytes>>>(ah, wt + OFF3, hbuf, a3s, a3d,
                                           NN, 64, 256);
        k_agg<1, true><<<NN, 32>>>(hbuf, b3, gm3, be3, ah, batch);
    }
    // ---- classifier
    k_mlp<<<GG, 128>>>(Wc1, bc1, Wc2, bc2, Wc3, bc3, outp);
}